// round 16
// baseline (speedup 1.0000x reference)
#include <cuda_runtime.h>
#include <cuda_bf16.h>
#include <math.h>
#include <stdint.h>

#define B_ 4
#define C_ 128
#define H_ 128
#define W_ 128
#define O_ 256
#define HW_ (H_*W_)
#define K2_ 9

// ---- scratch (device globals; no allocation allowed) ----
__device__ uint32_t g_xbf_hi[(size_t)B_*64*H_*132]; // bf16x2(ch pair) of x, width-padded
__device__ uint32_t g_xbf_lo[(size_t)B_*64*H_*132]; // bf16x2 residuals
__device__ float4   g_xf2  [(size_t)B_*64*H_*64];   // fp32 channel-pair interleaved x
__device__ uint32_t g_wbf_hi[16*40*32];             // offset w [q][tap*4+cp][n]
__device__ uint32_t g_wbf_lo[16*40*32];
__device__ float  g_om  [(size_t)B_*27*HW_];        // offset conv output
__device__ int4   g_sidx[B_*K2_*HW_];               // clamped corner indices
__device__ float4 g_swt [B_*K2_*HW_];               // bilinear weights*mask*valid
__device__ float  g_mid [(size_t)B_*C_*HW_];        // depthwise output

__device__ __forceinline__ uint32_t f2tf32(float f) {
    uint32_t r;
    asm("cvt.rna.tf32.f32 %0, %1;" : "=r"(r) : "f"(f));
    return r;
}
__device__ __forceinline__ uint32_t smem_u32(const void* p) {
    uint32_t a;
    asm("{ .reg .u64 t; cvta.to.shared.u64 t, %1; cvt.u32.u64 %0, t; }"
        : "=r"(a) : "l"(p));
    return a;
}
__device__ __forceinline__ void cp_async16(uint32_t dst, const void* src, int src_bytes) {
    asm volatile("cp.async.ca.shared.global [%0], [%1], 16, %2;"
                 :: "r"(dst), "l"(src), "r"(src_bytes) : "memory");
}
#define CP_COMMIT() asm volatile("cp.async.commit_group;" ::: "memory")
#define CP_WAIT(n)  asm volatile("cp.async.wait_group %0;" :: "n"(n) : "memory")

#define MMA_TF32(acc, af, bf)                                                 \
    asm volatile(                                                             \
        "mma.sync.aligned.m16n8k8.row.col.f32.tf32.tf32.f32 "                 \
        "{%0,%1,%2,%3}, {%4,%5,%6,%7}, {%8,%9}, {%0,%1,%2,%3};"               \
        : "+f"((acc)[0]), "+f"((acc)[1]), "+f"((acc)[2]), "+f"((acc)[3])      \
        : "r"((af)[0]), "r"((af)[1]), "r"((af)[2]), "r"((af)[3]),             \
          "r"((bf)[0]), "r"((bf)[1]))

#define MMA_BF16(acc, af, bf)                                                 \
    asm volatile(                                                             \
        "mma.sync.aligned.m16n8k16.row.col.f32.bf16.bf16.f32 "                \
        "{%0,%1,%2,%3}, {%4,%5,%6,%7}, {%8,%9}, {%0,%1,%2,%3};"               \
        : "+f"((acc)[0]), "+f"((acc)[1]), "+f"((acc)[2]), "+f"((acc)[3])      \
        : "r"((af)[0]), "r"((af)[1]), "r"((af)[2]), "r"((af)[3]),             \
          "r"((bf)[0]), "r"((bf)[1]))

__device__ __forceinline__ uint32_t pack_bf2(float a, float b) {
    uint16_t ua = __bfloat16_as_ushort(__float2bfloat16_rn(a));
    uint16_t ub = __bfloat16_as_ushort(__float2bfloat16_rn(b));
    return ((uint32_t)ub << 16) | (uint32_t)ua;
}
__device__ __forceinline__ float bf_hi(float v) {
    return __bfloat162float(__float2bfloat16_rn(v));
}

// ============================================================
// Pre-kernel A: pad x to width 132, pack channel-pairs as
// bf16x2 hi/lo for the offset conv, AND write an fp32
// channel-pair interleaved copy (width 128) for the sampler.
// Grid (B*64*H), block 132.
// ============================================================
__global__ void xpad_kernel(const float* __restrict__ x)
{
    const int r  = blockIdx.x;          // (b*64 + cp)*H + h
    const int j  = threadIdx.x;         // 0..131
    const int h  = r % H_;
    const int cp = (r / H_) % 64;
    const int b  = r / (H_*64);
    const int gx = j - 1;
    float v0 = 0.f, v1 = 0.f;
    if (gx >= 0 && gx < W_) {
        v0 = x[((size_t)(b*C_ + 2*cp    )*H_ + h)*W_ + gx];
        v1 = x[((size_t)(b*C_ + 2*cp + 1)*H_ + h)*W_ + gx];
    }
    float h0 = bf_hi(v0), h1 = bf_hi(v1);
    g_xbf_hi[(size_t)r*132 + j] = pack_bf2(h0, h1);
    g_xbf_lo[(size_t)r*132 + j] = pack_bf2(v0 - h0, v1 - h1);
    if (gx >= 0 && gx < W_) {
        float2* xf2 = (float2*)g_xf2;
        xf2[(size_t)r*W_ + gx] = make_float2(v0, v1);
    }
}

// ============================================================
// Pre-kernel B: offset weights -> [q][tap*4+cp][n=32] bf16x2
// (channel pair packed), hi/lo. tap 9 + n>=27 are zero pad.
// ============================================================
__global__ void wt_kernel(const float* __restrict__ w_off)
{
    const int idx = blockIdx.x*256 + threadIdx.x;   // 0..20479
    if (idx >= 16*40*32) return;
    const int n  = idx & 31;
    const int kk = idx >> 5;
    const int q  = kk / 40, r = kk % 40;
    const int t  = r >> 2, cp = r & 3;
    const int c0 = q*8 + 2*cp;
    float v0 = 0.f, v1 = 0.f;
    if (n < 27 && t < 9) {
        v0 = w_off[((size_t)n*C_ + c0    )*9 + t];
        v1 = w_off[((size_t)n*C_ + c0 + 1)*9 + t];
    }
    float h0 = bf_hi(v0), h1 = bf_hi(v1);
    g_wbf_hi[idx] = pack_bf2(h0, h1);
    g_wbf_lo[idx] = pack_bf2(v0 - h0, v1 - h1);
}

// ============================================================
// Kernel 1: offset conv as 3xBF16 mma implicit GEMM. (unchanged)
// ============================================================
#define XR 132
#define XSTP 536
#define XCHUNK (4*XSTP)
#define BSTR 40
#define BCH (40*BSTR)
#define OFF_SMEM ((4*XCHUNK + 4*BCH)*4)   // 59904 B

__global__ __launch_bounds__(256, 2) void offset_mma_kernel()
{
    extern __shared__ uint32_t sm[];
    const uint32_t sbase = smem_u32(sm);

    const int tid  = threadIdx.x;
    const int wid  = tid >> 5;
    const int lane = tid & 31;
    const int g    = lane >> 2;
    const int tg   = lane & 3;
    const int row_sel = wid >> 2;
    const int mbase   = (wid & 3) * 32;

    const int h0 = blockIdx.x * 2;
    const int b  = blockIdx.y;

    float acc[2][4][4];
#pragma unroll
    for (int i = 0; i < 2; i++)
#pragma unroll
        for (int j = 0; j < 4; j++)
#pragma unroll
            for (int r = 0; r < 4; r++) acc[i][j][r] = 0.f;

#define OFF_STAGE(q, buf) do {                                                \
    int cp0 = (q)*4;                                                          \
    uint32_t xh_b = sbase + (uint32_t)((buf)*2*XCHUNK*4);                     \
    uint32_t xl_b = xh_b + (uint32_t)(XCHUNK*4);                              \
    for (int i = tid; i < 4*4*33; i += 256) {                                 \
        int cp = i/132, rem = i - cp*132;                                     \
        int row = rem/33, v = rem - row*33;                                   \
        int gy = h0 - 1 + row;                                                \
        int ok = (gy >= 0 && gy < H_) ? 16 : 0;                               \
        int gyc = min(max(gy, 0), H_-1);                                      \
        size_t so = ((size_t)((b*64 + cp0 + cp)*H_ + gyc))*XR + v*4;          \
        uint32_t doff = (uint32_t)((cp*XSTP + row*XR + v*4)*4);               \
        cp_async16(xh_b + doff, g_xbf_hi + so, ok);                           \
        cp_async16(xl_b + doff, g_xbf_lo + so, ok);                           \
    }                                                                         \
    uint32_t bh_b = sbase + (uint32_t)((4*XCHUNK + (buf)*2*BCH)*4);           \
    uint32_t bl_b = bh_b + (uint32_t)(BCH*4);                                 \
    for (int i = tid; i < 320; i += 256) {                                    \
        int k = i >> 3, v = i & 7;                                            \
        int so = ((q)*40 + k)*32 + v*4;                                       \
        uint32_t doff = (uint32_t)((k*BSTR + v*4)*4);                         \
        cp_async16(bh_b + doff, g_wbf_hi + so, 16);                           \
        cp_async16(bl_b + doff, g_wbf_lo + so, 16);                           \
    }                                                                         \
} while (0)

    OFF_STAGE(0, 0);
    CP_COMMIT();

    for (int q = 0; q < 16; q++) {
        if (q < 15) { OFF_STAGE(q+1, (q+1)&1); CP_COMMIT(); CP_WAIT(1); }
        else        { CP_WAIT(0); }
        __syncthreads();

        const uint32_t* xh = sm + (q&1)*2*XCHUNK;
        const uint32_t* xl = xh + XCHUNK;
        const uint32_t* Bh = sm + 4*XCHUNK + (q&1)*2*BCH;
        const uint32_t* Bl = Bh + BCH;
#pragma unroll
        for (int ks = 0; ks < 5; ks++) {
            const int t0  = 2*ks;
            const int t1  = 2*ks + 1;
            const int t1a = (t1 > 8) ? 8 : t1;
            const int dy0 = t0/3,  dx0 = t0%3;
            const int dy1 = t1a/3, dx1 = t1a%3;
            const uint32_t fo0 = (uint32_t)(tg*XSTP + (row_sel+dy0)*XR + dx0);
            const uint32_t fo1 = (uint32_t)(tg*XSTP + (row_sel+dy1)*XR + dx1);
            uint32_t ah[2][4], al[2][4];
#pragma unroll
            for (int mf = 0; mf < 2; mf++) {
                int m = mbase + mf*16 + g;
                ah[mf][0] = xh[fo0 + m];
                ah[mf][1] = xh[fo0 + m + 8];
                ah[mf][2] = xh[fo1 + m];
                ah[mf][3] = xh[fo1 + m + 8];
                al[mf][0] = xl[fo0 + m];
                al[mf][1] = xl[fo0 + m + 8];
                al[mf][2] = xl[fo1 + m];
                al[mf][3] = xl[fo1 + m + 8];
            }
            uint32_t bh[4][2], bl[4][2];
#pragma unroll
            for (int nf = 0; nf < 4; nf++) {
                int r0 = (t0*4 + tg)*BSTR + nf*8 + g;
                int r1 = (t1*4 + tg)*BSTR + nf*8 + g;
                bh[nf][0] = Bh[r0];
                bh[nf][1] = Bh[r1];
                bl[nf][0] = Bl[r0];
                bl[nf][1] = Bl[r1];
            }
#pragma unroll
            for (int mf = 0; mf < 2; mf++)
#pragma unroll
                for (int nf = 0; nf < 4; nf++) {
                    MMA_BF16(acc[mf][nf], ah[mf], bh[nf]);
                    MMA_BF16(acc[mf][nf], ah[mf], bl[nf]);
                    MMA_BF16(acc[mf][nf], al[mf], bh[nf]);
                }
        }
        __syncthreads();
    }

    const int p_base = (h0 + row_sel) * W_;
#pragma unroll
    for (int nf = 0; nf < 4; nf++) {
        int n0 = nf*8 + 2*tg;
#pragma unroll
        for (int mf = 0; mf < 2; mf++) {
            int m = mbase + mf*16 + g;
            if (n0 < 27) {
                float* op = g_om + ((size_t)(b*27 + n0))*HW_ + p_base;
                op[m]     = acc[mf][nf][0];
                op[m + 8] = acc[mf][nf][2];
            }
            if (n0 + 1 < 27) {
                float* op = g_om + ((size_t)(b*27 + n0 + 1))*HW_ + p_base;
                op[m]     = acc[mf][nf][1];
                op[m + 8] = acc[mf][nf][3];
            }
        }
    }
}

// ============================================================
// Kernel 1b: bias + bilinear sampling params from g_om. (unchanged)
// ============================================================
__global__ __launch_bounds__(256) void param_kernel(
    const float* __restrict__ b_off)
{
    const int p = blockIdx.x * 256 + threadIdx.x;
    const int b = blockIdx.y;
    const int h = p / W_;
    const int w = p % W_;

    float om[27];
#pragma unroll
    for (int o = 0; o < 27; o++)
        om[o] = g_om[((size_t)(b*27 + o))*HW_ + p] + __ldg(&b_off[o]);

#pragma unroll
    for (int k = 0; k < 9; k++) {
        float dyv = om[2*k];
        float dxv = om[2*k + 1];
        float m   = 1.f / (1.f + expf(-om[18 + k]));

        float py = (float)h + (float)(k/3 - 1) + dyv;
        float px = (float)w + (float)(k%3 - 1) + dxv;
        float y0f = floorf(py), x0f = floorf(px);
        int   y0 = (int)y0f,   x0 = (int)x0f;
        int   y1 = y0 + 1,     x1 = x0 + 1;
        float wy = py - y0f,   wx = px - x0f;

        float vy0 = (y0 >= 0 && y0 < H_) ? 1.f : 0.f;
        float vy1 = (y1 >= 0 && y1 < H_) ? 1.f : 0.f;
        float vx0 = (x0 >= 0 && x0 < W_) ? 1.f : 0.f;
        float vx1 = (x1 >= 0 && x1 < W_) ? 1.f : 0.f;

        int cy0 = min(max(y0, 0), H_-1);
        int cy1 = min(max(y1, 0), H_-1);
        int cx0 = min(max(x0, 0), W_-1);
        int cx1 = min(max(x1, 0), W_-1);

        int4 id;
        id.x = cy0*W_ + cx0;
        id.y = cy0*W_ + cx1;
        id.z = cy1*W_ + cx0;
        id.w = cy1*W_ + cx1;
        float4 wt;
        wt.x = (1.f-wy)*(1.f-wx) * m * vy0 * vx0;
        wt.y = (1.f-wy)*wx       * m * vy0 * vx1;
        wt.z = wy*(1.f-wx)       * m * vy1 * vx0;
        wt.w = wy*wx             * m * vy1 * vx1;

        int gidx = (b*K2_ + k)*HW_ + p;
        g_sidx[gidx] = id;
        g_swt [gidx] = wt;
    }
}

// ============================================================
// Kernel 2: deformable gather + depthwise via SMEM row-window,
// v4: fp32 channel-PAIR window (float2). Each tap does 4 LDS.64
// serving both channels -> per-channel LDS instr count halved,
// barrier count halved (32 pair iterations). Math is expression-
// identical per channel -> bit-identical output vs v3.
// ============================================================
#define WIN 16
#define WTOP 7            // window = [h-7, h+8)

__global__ __launch_bounds__(128) void sample_kernel(
    const float* __restrict__ x,
    const float* __restrict__ w_dw,
    const float* __restrict__ b_dw)
{
    __shared__ float2 xs[2][WIN*W_];   // 2 x 16KB
    __shared__ float sdw[64*K2_];

    const int h   = blockIdx.x;
    const int b   = blockIdx.y;
    const int c0  = blockIdx.z * 64;        // channel base
    const int cp0 = blockIdx.z * 32;        // pair base
    const int tx  = threadIdx.x;
    const int p   = h * W_ + tx;
    const int wbase = h - WTOP;

    for (int i = tx; i < 64*K2_; i += 128) sdw[i] = w_dw[c0*K2_ + i];

    int   off00[9], dxo[9], dyo[9];
    float4 wt[9];
    bool lane_in = true;
#pragma unroll
    for (int k = 0; k < 9; k++) {
        int4 id = g_sidx[(b*K2_ + k)*HW_ + p];
        wt[k]   = g_swt [(b*K2_ + k)*HW_ + p];
        int cy0 = id.x >> 7, cx0 = id.x & 127;
        int cy1 = id.z >> 7, cx1 = id.y & 127;
        int s0 = cy0 - wbase;
        int s1 = cy1 - wbase;
        bool in = (s0 >= 0) && (s1 < WIN);
        lane_in = lane_in && in;
        int s0c = min(max(s0, 0), WIN-1);
        int s1c = min(max(s1, 0), WIN-1);
        off00[k] = s0c*W_ + cx0;
        dxo[k]   = cx1 - cx0;
        dyo[k]   = (s1c - s0c)*W_;
    }
    const bool warp_oow = __any_sync(0xffffffffu, !lane_in);

    const float*  __restrict__ xc  = x + (size_t)(b*C_)*HW_;
    const float2* __restrict__ xf2 = (const float2*)g_xf2 + (size_t)(b*64)*HW_;

    // stage one channel-pair's 16-row float2 window: 16KB = 1024 x 16B
#define SMP_STAGE(cp, buf) do {                                               \
    uint32_t dstb = smem_u32(&xs[buf][0]);                                    \
    const float2* src0 = xf2 + (size_t)(cp0 + (cp))*HW_;                      \
    _Pragma("unroll")                                                         \
    for (int l = 0; l < 8; l++) {                                             \
        int idx = tx + 128*l;                                                 \
        int row = idx >> 6, v = idx & 63;   /* 64 x 16B chunks per row */     \
        int gy = min(max(wbase + row, 0), H_-1);                              \
        cp_async16(dstb + (uint32_t)(row*1024 + v*16),                        \
                   src0 + (size_t)gy*W_ + v*2, 16);                           \
    }                                                                         \
} while (0)

    SMP_STAGE(0, 0);
    CP_COMMIT();

    for (int cp = 0; cp < 32; cp++) {
        const int buf = cp & 1;
        if (cp < 31) { SMP_STAGE(cp+1, buf ^ 1); CP_COMMIT(); CP_WAIT(1); }
        else         { CP_WAIT(0); }
        __syncthreads();

        const float2* __restrict__ xsb = xs[buf];
        const int cA = 2*cp, cB = 2*cp + 1;
        float acc0 = __ldg(&b_dw[c0 + cA]);
        float acc1 = __ldg(&b_dw[c0 + cB]);
#pragma unroll
        for (int k = 0; k < 9; k++) {
            int o = off00[k];
            float2 v00 = xsb[o];
            float2 v01 = xsb[o + dxo[k]];
            float2 v10 = xsb[o + dyo[k]];
            float2 v11 = xsb[o + dyo[k] + dxo[k]];
            float s0 = wt[k].x * v00.x + wt[k].y * v01.x
                     + wt[k].z * v10.x + wt[k].w * v11.x;
            float s1 = wt[k].x * v00.y + wt[k].y * v01.y
                     + wt[k].z * v10.y + wt[k].w * v11.y;
            acc0 += sdw[cA*9 + k] * s0;
            acc1 += sdw[cB*9 + k] * s1;
        }

        if (warp_oow) {                 // warp-uniform, ~never taken
            if (!lane_in) {
                const float* __restrict__ xbA = xc + (size_t)(c0 + cA)*HW_;
                const float* __restrict__ xbB = xc + (size_t)(c0 + cB)*HW_;
                acc0 = __ldg(&b_dw[c0 + cA]);
                acc1 = __ldg(&b_dw[c0 + cB]);
#pragma unroll
                for (int k = 0; k < 9; k++) {
                    int4 id = g_sidx[(b*K2_ + k)*HW_ + p];
                    float sA = wt[k].x * __ldg(xbA + id.x)
                             + wt[k].y * __ldg(xbA + id.y)
                             + wt[k].z * __ldg(xbA + id.z)
                             + wt[k].w * __ldg(xbA + id.w);
                    float sB = wt[k].x * __ldg(xbB + id.x)
                             + wt[k].y * __ldg(xbB + id.y)
                             + wt[k].z * __ldg(xbB + id.z)
                             + wt[k].w * __ldg(xbB + id.w);
                    acc0 += sdw[cA*9 + k] * sA;
                    acc1 += sdw[cB*9 + k] * sB;
                }
            }
        }

        g_mid[(size_t)(b*C_ + c0 + cA)*HW_ + p] = acc0;
        g_mid[(size_t)(b*C_ + c0 + cB)*HW_ + p] = acc1;
        __syncthreads();
    }
}

// ============================================================
// Kernel 3: pointwise GEMM via mma.sync tf32. (unchanged)
// ============================================================
#define KC 32
#define A_STRIDE 136
#define B_STRIDE 36
#define A_BUF (KC*A_STRIDE)
#define B_BUF (128*B_STRIDE)
#define PW_SMEM ((2*A_BUF + 2*B_BUF)*4)

__global__ __launch_bounds__(256) void pw_mma_kernel(
    const float* __restrict__ w_pw,
    const float* __restrict__ b_pw,
    float* __restrict__ out)
{
    extern __shared__ float smem[];
    float* A_s = smem;
    float* B_s = smem + 2*A_BUF;

    const int tid = threadIdx.x;
    const int wid = tid >> 5;
    const int lane = tid & 31;
    const int g  = lane >> 2;
    const int tg = lane & 3;

    const int wm = wid & 1;
    const int wn = wid >> 1;

    const int m0 = blockIdx.x * 128;
    const int b  = m0 / HW_;
    const int p0 = m0 % HW_;
    const int o0 = blockIdx.y * 128;

    float acc[4][4][4];
#pragma unroll
    for (int i = 0; i < 4; i++)
#pragma unroll
        for (int j = 0; j < 4; j++)
#pragma unroll
            for (int r = 0; r < 4; r++) acc[i][j][r] = 0.f;

    float4 pa[4], pb[4];

#define LDG_CHUNK(q)                                                          \
    {                                                                         \
        _Pragma("unroll")                                                     \
        for (int i = 0; i < 4; i++) {                                         \
            int idx = tid + 256*i;                                            \
            int row = idx >> 5, c4 = idx & 31;                                \
            pa[i] = *(const float4*)(g_mid +                                  \
                     (size_t)(b*C_ + (q)*KC + row)*HW_ + p0 + c4*4);          \
            int n = idx >> 3, kq = idx & 7;                                   \
            pb[i] = *(const float4*)(w_pw +                                   \
                     (size_t)(o0 + n)*C_ + (q)*KC + kq*4);                    \
        }                                                                     \
    }
#define STS_CHUNK(buf)                                                        \
    {                                                                         \
        _Pragma("unroll")                                                     \
        for (int i = 0; i < 4; i++) {                                         \
            int idx = tid + 256*i;                                            \
            int row = idx >> 5, c4 = idx & 31;                                \
            float* da = &A_s[(buf)*A_BUF + row*A_STRIDE + c4*4];              \
            da[0] = __uint_as_float(f2tf32(pa[i].x));                         \
            da[1] = __uint_as_float(f2tf32(pa[i].y));                         \
            da[2] = __uint_as_float(f2tf32(pa[i].z));                         \
            da[3] = __uint_as_float(f2tf32(pa[i].w));                         \
            int n = idx >> 3, kq = idx & 7;                                   \
            float* db = &B_s[(buf)*B_BUF + n*B_STRIDE + kq*4];                \
            db[0] = __uint_as_float(f2tf32(pb[i].x));                         \
            db[1] = __uint_as_float(f2tf32(pb[i].y));                         \
            db[2] = __uint_as_float(f2tf32(pb[i].z));                         \
            db[3] = __uint_as_float(f2tf32(pb[i].w));                         \
        }                                                                     \
    }

    LDG_CHUNK(0);
    STS_CHUNK(0);
    __syncthreads();

    for (int q = 0; q < C_/KC; q++) {
        const int buf = q & 1;
        if (q < C_/KC - 1) LDG_CHUNK(q + 1);

        const float* Ab = A_s + buf*A_BUF;
        const float* Bb = B_s + buf*B_BUF;
#pragma unroll
        for (int ks = 0; ks < KC/8; ks++) {
            uint32_t af[4][4];
#pragma unroll
            for (int mf = 0; mf < 4; mf++) {
                int k = ks*8 + tg;
                int m = wm*64 + mf*16 + g;
                af[mf][0] = __float_as_uint(Ab[k*A_STRIDE + m]);
                af[mf][1] = __float_as_uint(Ab[k*A_STRIDE + m + 8]);
                af[mf][2] = __float_as_uint(Ab[(k+4)*A_STRIDE + m]);
                af[mf][3] = __float_as_uint(Ab[(k+4)*A_STRIDE + m + 8]);
            }
            uint32_t bf[4][2];
#pragma unroll
            for (int nf = 0; nf < 4; nf++) {
                int n = wn*32 + nf*8 + g;
                bf[nf][0] = __float_as_uint(Bb[n*B_STRIDE + ks*8 + tg]);
                bf[nf][1] = __float_as_uint(Bb[n*B_STRIDE + ks*8 + tg + 4]);
            }
#pragma unroll
            for (int mf = 0; mf < 4; mf++)
#pragma unroll
                for (int nf = 0; nf < 4; nf++)
                    MMA_TF32(acc[mf][nf], af[mf], bf[nf]);
        }

        if (q < C_/KC - 1) {
            STS_CHUNK(buf ^ 1);
            __syncthreads();
        }
    }

#pragma unroll
    for (int nf = 0; nf < 4; nf++) {
        int oc = o0 + wn*32 + nf*8 + 2*tg;
        float bp0 = __ldg(&b_pw[oc]);
        float bp1 = __ldg(&b_pw[oc + 1]);
        float* o_ptr0 = out + (size_t)(b*O_ + oc    )*HW_ + p0;
        float* o_ptr1 = out + (size_t)(b*O_ + oc + 1)*HW_ + p0;
#pragma unroll
        for (int mf = 0; mf < 4; mf++) {
            int m = wm*64 + mf*16 + g;
            o_ptr0[m]     = acc[mf][nf][0] + bp0;
            o_ptr1[m]     = acc[mf][nf][1] + bp1;
            o_ptr0[m + 8] = acc[mf][nf][2] + bp0;
            o_ptr1[m + 8] = acc[mf][nf][3] + bp1;
        }
    }
}

// ============================================================
extern "C" void kernel_launch(void* const* d_in, const int* in_sizes, int n_in,
                              void* d_out, int out_size)
{
    const float* x     = (const float*)d_in[0];
    const float* w_off = (const float*)d_in[1];
    const float* b_off = (const float*)d_in[2];
    const float* w_dw  = (const float*)d_in[3];
    const float* b_dw  = (const float*)d_in[4];
    const float* w_pw  = (const float*)d_in[5];
    const float* b_pw  = (const float*)d_in[6];
    float* out = (float*)d_out;

    cudaFuncSetAttribute(pw_mma_kernel,
                         cudaFuncAttributeMaxDynamicSharedMemorySize, PW_SMEM);
    cudaFuncSetAttribute(offset_mma_kernel,
                         cudaFuncAttributeMaxDynamicSharedMemorySize, OFF_SMEM);

    xpad_kernel<<<B_*64*H_, 132>>>(x);
    wt_kernel<<<80, 256>>>(w_off);

    dim3 g1(H_/2, B_);
    offset_mma_kernel<<<g1, 256, OFF_SMEM>>>();

    dim3 g1b(HW_/256, B_);
    param_kernel<<<g1b, 256>>>(b_off);

    dim3 g2(H_, B_, 2);
    sample_kernel<<<g2, 128>>>(x, w_dw, b_dw);

    dim3 g3((B_*HW_)/128, O_/128);
    pw_mma_kernel<<<g3, 256, PW_SMEM>>>(w_pw, b_pw, out);
}

// round 17
// speedup vs baseline: 1.2125x; 1.2125x over previous
#include <cuda_runtime.h>
#include <cuda_bf16.h>
#include <math.h>
#include <stdint.h>

#define B_ 4
#define C_ 128
#define H_ 128
#define W_ 128
#define O_ 256
#define HW_ (H_*W_)
#define K2_ 9

// ---- scratch (device globals; no allocation allowed) ----
__device__ uint32_t g_xbf_hi[(size_t)B_*64*H_*132]; // bf16x2(ch pair) of x, width-padded
__device__ uint32_t g_xbf_lo[(size_t)B_*64*H_*132]; // bf16x2 residuals
__device__ uint32_t g_wbf_hi[16*40*32];             // offset w [q][tap*4+cp][n]
__device__ uint32_t g_wbf_lo[16*40*32];
__device__ float  g_xhwc[(size_t)B_*HW_*C_];        // x transposed to [p][c]
__device__ float  g_om  [(size_t)B_*27*HW_];        // offset conv output
__device__ int4   g_sidx[B_*K2_*HW_];               // clamped corner indices
__device__ float4 g_swt [B_*K2_*HW_];               // bilinear weights*mask*valid
__device__ float  g_midh[(size_t)B_*HW_*C_];        // depthwise output, HWC

__device__ __forceinline__ uint32_t f2tf32(float f) {
    uint32_t r;
    asm("cvt.rna.tf32.f32 %0, %1;" : "=r"(r) : "f"(f));
    return r;
}
__device__ __forceinline__ uint32_t smem_u32(const void* p) {
    uint32_t a;
    asm("{ .reg .u64 t; cvta.to.shared.u64 t, %1; cvt.u32.u64 %0, t; }"
        : "=r"(a) : "l"(p));
    return a;
}
__device__ __forceinline__ void cp_async16(uint32_t dst, const void* src, int src_bytes) {
    asm volatile("cp.async.ca.shared.global [%0], [%1], 16, %2;"
                 :: "r"(dst), "l"(src), "r"(src_bytes) : "memory");
}
#define CP_COMMIT() asm volatile("cp.async.commit_group;" ::: "memory")
#define CP_WAIT(n)  asm volatile("cp.async.wait_group %0;" :: "n"(n) : "memory")

#define MMA_TF32(acc, af, bf)                                                 \
    asm volatile(                                                             \
        "mma.sync.aligned.m16n8k8.row.col.f32.tf32.tf32.f32 "                 \
        "{%0,%1,%2,%3}, {%4,%5,%6,%7}, {%8,%9}, {%0,%1,%2,%3};"               \
        : "+f"((acc)[0]), "+f"((acc)[1]), "+f"((acc)[2]), "+f"((acc)[3])      \
        : "r"((af)[0]), "r"((af)[1]), "r"((af)[2]), "r"((af)[3]),             \
          "r"((bf)[0]), "r"((bf)[1]))

#define MMA_BF16(acc, af, bf)                                                 \
    asm volatile(                                                             \
        "mma.sync.aligned.m16n8k16.row.col.f32.bf16.bf16.f32 "                \
        "{%0,%1,%2,%3}, {%4,%5,%6,%7}, {%8,%9}, {%0,%1,%2,%3};"               \
        : "+f"((acc)[0]), "+f"((acc)[1]), "+f"((acc)[2]), "+f"((acc)[3])      \
        : "r"((af)[0]), "r"((af)[1]), "r"((af)[2]), "r"((af)[3]),             \
          "r"((bf)[0]), "r"((bf)[1]))

__device__ __forceinline__ uint32_t pack_bf2(float a, float b) {
    uint16_t ua = __bfloat16_as_ushort(__float2bfloat16_rn(a));
    uint16_t ub = __bfloat16_as_ushort(__float2bfloat16_rn(b));
    return ((uint32_t)ub << 16) | (uint32_t)ua;
}
__device__ __forceinline__ float bf_hi(float v) {
    return __bfloat162float(__float2bfloat16_rn(v));
}

// ============================================================
// Pre-kernel A: pad x to width 132, pack channel-pairs as
// bf16x2 hi/lo for the offset conv. Grid (B*64*H), block 132.
// ============================================================
__global__ void xpad_kernel(const float* __restrict__ x)
{
    const int r  = blockIdx.x;          // (b*64 + cp)*H + h
    const int j  = threadIdx.x;         // 0..131
    const int h  = r % H_;
    const int cp = (r / H_) % 64;
    const int b  = r / (H_*64);
    const int gx = j - 1;
    float v0 = 0.f, v1 = 0.f;
    if (gx >= 0 && gx < W_) {
        v0 = x[((size_t)(b*C_ + 2*cp    )*H_ + h)*W_ + gx];
        v1 = x[((size_t)(b*C_ + 2*cp + 1)*H_ + h)*W_ + gx];
    }
    float h0 = bf_hi(v0), h1 = bf_hi(v1);
    g_xbf_hi[(size_t)r*132 + j] = pack_bf2(h0, h1);
    g_xbf_lo[(size_t)r*132 + j] = pack_bf2(v0 - h0, v1 - h1);
}

// ============================================================
// Pre-kernel A2: transpose x CHW -> HWC (smem-tiled).
// Grid (HW/64, C/32, B), block 256.
// ============================================================
__global__ __launch_bounds__(256) void hwc_kernel(const float* __restrict__ x)
{
    __shared__ float t[32][65];
    const int p0 = blockIdx.x * 64;
    const int c0 = blockIdx.y * 32;
    const int b  = blockIdx.z;
    const int tid = threadIdx.x;
    for (int i = tid; i < 2048; i += 256) {
        int c = i >> 6, p = i & 63;
        t[c][p] = x[((size_t)(b*C_ + c0 + c))*HW_ + p0 + p];
    }
    __syncthreads();
    for (int i = tid; i < 2048; i += 256) {
        int p = i >> 5, c = i & 31;
        g_xhwc[((size_t)b*HW_ + p0 + p)*C_ + c0 + c] = t[c][p];
    }
}

// ============================================================
// Pre-kernel B: offset weights -> [q][tap*4+cp][n=32] bf16x2
// (channel pair packed), hi/lo. tap 9 + n>=27 are zero pad.
// ============================================================
__global__ void wt_kernel(const float* __restrict__ w_off)
{
    const int idx = blockIdx.x*256 + threadIdx.x;   // 0..20479
    if (idx >= 16*40*32) return;
    const int n  = idx & 31;
    const int kk = idx >> 5;
    const int q  = kk / 40, r = kk % 40;
    const int t  = r >> 2, cp = r & 3;
    const int c0 = q*8 + 2*cp;
    float v0 = 0.f, v1 = 0.f;
    if (n < 27 && t < 9) {
        v0 = w_off[((size_t)n*C_ + c0    )*9 + t];
        v1 = w_off[((size_t)n*C_ + c0 + 1)*9 + t];
    }
    float h0 = bf_hi(v0), h1 = bf_hi(v1);
    g_wbf_hi[idx] = pack_bf2(h0, h1);
    g_wbf_lo[idx] = pack_bf2(v0 - h0, v1 - h1);
}

// ============================================================
// Kernel 1: offset conv as 3xBF16 mma implicit GEMM. (unchanged)
// ============================================================
#define XR 132
#define XSTP 536
#define XCHUNK (4*XSTP)
#define BSTR 40
#define BCH (40*BSTR)
#define OFF_SMEM ((4*XCHUNK + 4*BCH)*4)   // 59904 B

__global__ __launch_bounds__(256, 2) void offset_mma_kernel()
{
    extern __shared__ uint32_t sm[];
    const uint32_t sbase = smem_u32(sm);

    const int tid  = threadIdx.x;
    const int wid  = tid >> 5;
    const int lane = tid & 31;
    const int g    = lane >> 2;
    const int tg   = lane & 3;
    const int row_sel = wid >> 2;
    const int mbase   = (wid & 3) * 32;

    const int h0 = blockIdx.x * 2;
    const int b  = blockIdx.y;

    float acc[2][4][4];
#pragma unroll
    for (int i = 0; i < 2; i++)
#pragma unroll
        for (int j = 0; j < 4; j++)
#pragma unroll
            for (int r = 0; r < 4; r++) acc[i][j][r] = 0.f;

#define OFF_STAGE(q, buf) do {                                                \
    int cp0 = (q)*4;                                                          \
    uint32_t xh_b = sbase + (uint32_t)((buf)*2*XCHUNK*4);                     \
    uint32_t xl_b = xh_b + (uint32_t)(XCHUNK*4);                              \
    for (int i = tid; i < 4*4*33; i += 256) {                                 \
        int cp = i/132, rem = i - cp*132;                                     \
        int row = rem/33, v = rem - row*33;                                   \
        int gy = h0 - 1 + row;                                                \
        int ok = (gy >= 0 && gy < H_) ? 16 : 0;                               \
        int gyc = min(max(gy, 0), H_-1);                                      \
        size_t so = ((size_t)((b*64 + cp0 + cp)*H_ + gyc))*XR + v*4;          \
        uint32_t doff = (uint32_t)((cp*XSTP + row*XR + v*4)*4);               \
        cp_async16(xh_b + doff, g_xbf_hi + so, ok);                           \
        cp_async16(xl_b + doff, g_xbf_lo + so, ok);                           \
    }                                                                         \
    uint32_t bh_b = sbase + (uint32_t)((4*XCHUNK + (buf)*2*BCH)*4);           \
    uint32_t bl_b = bh_b + (uint32_t)(BCH*4);                                 \
    for (int i = tid; i < 320; i += 256) {                                    \
        int k = i >> 3, v = i & 7;                                            \
        int so = ((q)*40 + k)*32 + v*4;                                       \
        uint32_t doff = (uint32_t)((k*BSTR + v*4)*4);                         \
        cp_async16(bh_b + doff, g_wbf_hi + so, 16);                           \
        cp_async16(bl_b + doff, g_wbf_lo + so, 16);                           \
    }                                                                         \
} while (0)

    OFF_STAGE(0, 0);
    CP_COMMIT();

    for (int q = 0; q < 16; q++) {
        if (q < 15) { OFF_STAGE(q+1, (q+1)&1); CP_COMMIT(); CP_WAIT(1); }
        else        { CP_WAIT(0); }
        __syncthreads();

        const uint32_t* xh = sm + (q&1)*2*XCHUNK;
        const uint32_t* xl = xh + XCHUNK;
        const uint32_t* Bh = sm + 4*XCHUNK + (q&1)*2*BCH;
        const uint32_t* Bl = Bh + BCH;
#pragma unroll
        for (int ks = 0; ks < 5; ks++) {
            const int t0  = 2*ks;
            const int t1  = 2*ks + 1;
            const int t1a = (t1 > 8) ? 8 : t1;
            const int dy0 = t0/3,  dx0 = t0%3;
            const int dy1 = t1a/3, dx1 = t1a%3;
            const uint32_t fo0 = (uint32_t)(tg*XSTP + (row_sel+dy0)*XR + dx0);
            const uint32_t fo1 = (uint32_t)(tg*XSTP + (row_sel+dy1)*XR + dx1);
            uint32_t ah[2][4], al[2][4];
#pragma unroll
            for (int mf = 0; mf < 2; mf++) {
                int m = mbase + mf*16 + g;
                ah[mf][0] = xh[fo0 + m];
                ah[mf][1] = xh[fo0 + m + 8];
                ah[mf][2] = xh[fo1 + m];
                ah[mf][3] = xh[fo1 + m + 8];
                al[mf][0] = xl[fo0 + m];
                al[mf][1] = xl[fo0 + m + 8];
                al[mf][2] = xl[fo1 + m];
                al[mf][3] = xl[fo1 + m + 8];
            }
            uint32_t bh[4][2], bl[4][2];
#pragma unroll
            for (int nf = 0; nf < 4; nf++) {
                int r0 = (t0*4 + tg)*BSTR + nf*8 + g;
                int r1 = (t1*4 + tg)*BSTR + nf*8 + g;
                bh[nf][0] = Bh[r0];
                bh[nf][1] = Bh[r1];
                bl[nf][0] = Bl[r0];
                bl[nf][1] = Bl[r1];
            }
#pragma unroll
            for (int mf = 0; mf < 2; mf++)
#pragma unroll
                for (int nf = 0; nf < 4; nf++) {
                    MMA_BF16(acc[mf][nf], ah[mf], bh[nf]);
                    MMA_BF16(acc[mf][nf], ah[mf], bl[nf]);
                    MMA_BF16(acc[mf][nf], al[mf], bh[nf]);
                }
        }
        __syncthreads();
    }

    const int p_base = (h0 + row_sel) * W_;
#pragma unroll
    for (int nf = 0; nf < 4; nf++) {
        int n0 = nf*8 + 2*tg;
#pragma unroll
        for (int mf = 0; mf < 2; mf++) {
            int m = mbase + mf*16 + g;
            if (n0 < 27) {
                float* op = g_om + ((size_t)(b*27 + n0))*HW_ + p_base;
                op[m]     = acc[mf][nf][0];
                op[m + 8] = acc[mf][nf][2];
            }
            if (n0 + 1 < 27) {
                float* op = g_om + ((size_t)(b*27 + n0 + 1))*HW_ + p_base;
                op[m]     = acc[mf][nf][1];
                op[m + 8] = acc[mf][nf][3];
            }
        }
    }
}

// ============================================================
// Kernel 1b: bias + bilinear sampling params from g_om. (unchanged)
// ============================================================
__global__ __launch_bounds__(256) void param_kernel(
    const float* __restrict__ b_off)
{
    const int p = blockIdx.x * 256 + threadIdx.x;
    const int b = blockIdx.y;
    const int h = p / W_;
    const int w = p % W_;

    float om[27];
#pragma unroll
    for (int o = 0; o < 27; o++)
        om[o] = g_om[((size_t)(b*27 + o))*HW_ + p] + __ldg(&b_off[o]);

#pragma unroll
    for (int k = 0; k < 9; k++) {
        float dyv = om[2*k];
        float dxv = om[2*k + 1];
        float m   = 1.f / (1.f + expf(-om[18 + k]));

        float py = (float)h + (float)(k/3 - 1) + dyv;
        float px = (float)w + (float)(k%3 - 1) + dxv;
        float y0f = floorf(py), x0f = floorf(px);
        int   y0 = (int)y0f,   x0 = (int)x0f;
        int   y1 = y0 + 1,     x1 = x0 + 1;
        float wy = py - y0f,   wx = px - x0f;

        float vy0 = (y0 >= 0 && y0 < H_) ? 1.f : 0.f;
        float vy1 = (y1 >= 0 && y1 < H_) ? 1.f : 0.f;
        float vx0 = (x0 >= 0 && x0 < W_) ? 1.f : 0.f;
        float vx1 = (x1 >= 0 && x1 < W_) ? 1.f : 0.f;

        int cy0 = min(max(y0, 0), H_-1);
        int cy1 = min(max(y1, 0), H_-1);
        int cx0 = min(max(x0, 0), W_-1);
        int cx1 = min(max(x1, 0), W_-1);

        int4 id;
        id.x = cy0*W_ + cx0;
        id.y = cy0*W_ + cx1;
        id.z = cy1*W_ + cx0;
        id.w = cy1*W_ + cx1;
        float4 wt;
        wt.x = (1.f-wy)*(1.f-wx) * m * vy0 * vx0;
        wt.y = (1.f-wy)*wx       * m * vy0 * vx1;
        wt.z = wy*(1.f-wx)       * m * vy1 * vx0;
        wt.w = wy*wx             * m * vy1 * vx1;

        int gidx = (b*K2_ + k)*HW_ + p;
        g_sidx[gidx] = id;
        g_swt [gidx] = wt;
    }
}

// ============================================================
// Kernel 2 (v5): HWC gather. Warp = 1 pixel, lane = 4 channels;
// one warp-LDG.128 per corner fetches all 128 channels, fully
// coalesced. 4 pixels per warp amortize the depthwise weights.
// No smem window, no barriers in the loop, MLP = 36 LDGs.
// Grid (HW/32, B), block 256 (8 warps x 4 px).
// ============================================================
__global__ __launch_bounds__(256) void sample_kernel(
    const float* __restrict__ w_dw,
    const float* __restrict__ b_dw)
{
    __shared__ float sdwT[9*128];      // [k][c] transposed depthwise weights

    const int tid  = threadIdx.x;
    const int lane = tid & 31;
    const int warp = tid >> 5;
    const int b    = blockIdx.y;
    const int pw0  = blockIdx.x * 32 + warp * 4;

    for (int i = tid; i < C_*K2_; i += 256) {
        int c = i / 9, k = i - c*9;
        sdwT[k*128 + c] = w_dw[i];
    }
    __syncthreads();

    float4 dw[9];
#pragma unroll
    for (int k = 0; k < 9; k++)
        dw[k] = *(const float4*)&sdwT[k*128 + 4*lane];
    const float4 bd = __ldg(((const float4*)b_dw) + lane);

    const float* __restrict__ xh = g_xhwc + (size_t)b*HW_*C_;

#pragma unroll
    for (int px = 0; px < 4; px++) {
        const int p = pw0 + px;
        float a0 = bd.x, a1 = bd.y, a2 = bd.z, a3 = bd.w;
#pragma unroll
        for (int k = 0; k < 9; k++) {
            int4   id = __ldg(&g_sidx[(b*K2_ + k)*HW_ + p]);
            float4 wt = __ldg(&g_swt [(b*K2_ + k)*HW_ + p]);
            float4 v00 = __ldg((const float4*)(xh + (size_t)id.x*C_) + lane);
            float4 v01 = __ldg((const float4*)(xh + (size_t)id.y*C_) + lane);
            float4 v10 = __ldg((const float4*)(xh + (size_t)id.z*C_) + lane);
            float4 v11 = __ldg((const float4*)(xh + (size_t)id.w*C_) + lane);
            float s0 = wt.x*v00.x + wt.y*v01.x + wt.z*v10.x + wt.w*v11.x;
            float s1 = wt.x*v00.y + wt.y*v01.y + wt.z*v10.y + wt.w*v11.y;
            float s2 = wt.x*v00.z + wt.y*v01.z + wt.z*v10.z + wt.w*v11.z;
            float s3 = wt.x*v00.w + wt.y*v01.w + wt.z*v10.w + wt.w*v11.w;
            a0 += dw[k].x * s0;
            a1 += dw[k].y * s1;
            a2 += dw[k].z * s2;
            a3 += dw[k].w * s3;
        }
        *(float4*)(g_midh + (size_t)(b*HW_ + p)*C_ + 4*lane) =
            make_float4(a0, a1, a2, a3);
    }
}

// ============================================================
// Kernel 3: pointwise GEMM via mma.sync tf32; A read from HWC
// g_midh. A_s layout [m][k] stride 36 -> frag LDS bank 4g+tg,
// conflict-free. B path unchanged.
// ============================================================
#define KC 32
#define A_STRIDE 36
#define B_STRIDE 36
#define A_BUF (128*A_STRIDE)
#define B_BUF (128*B_STRIDE)
#define PW_SMEM ((2*A_BUF + 2*B_BUF)*4)   // 73728 B

__global__ __launch_bounds__(256) void pw_mma_kernel(
    const float* __restrict__ w_pw,
    const float* __restrict__ b_pw,
    float* __restrict__ out)
{
    extern __shared__ float smem[];
    float* A_s = smem;
    float* B_s = smem + 2*A_BUF;

    const int tid = threadIdx.x;
    const int wid = tid >> 5;
    const int lane = tid & 31;
    const int g  = lane >> 2;
    const int tg = lane & 3;

    const int wm = wid & 1;
    const int wn = wid >> 1;

    const int m0 = blockIdx.x * 128;       // global pixel (b*HW + p)
    const int b  = m0 / HW_;
    const int p0 = m0 % HW_;
    const int o0 = blockIdx.y * 128;

    float acc[4][4][4];
#pragma unroll
    for (int i = 0; i < 4; i++)
#pragma unroll
        for (int j = 0; j < 4; j++)
#pragma unroll
            for (int r = 0; r < 4; r++) acc[i][j][r] = 0.f;

    float4 pa[4], pb[4];

#define LDG_CHUNK(q)                                                          \
    {                                                                         \
        _Pragma("unroll")                                                     \
        for (int i = 0; i < 4; i++) {                                         \
            int idx = tid + 256*i;                                            \
            int px = idx >> 3, c8 = idx & 7;                                  \
            pa[i] = *(const float4*)(g_midh +                                 \
                     (size_t)(m0 + px)*C_ + (q)*KC + c8*4);                   \
            int n = idx >> 3, kq = idx & 7;                                   \
            pb[i] = *(const float4*)(w_pw +                                   \
                     (size_t)(o0 + n)*C_ + (q)*KC + kq*4);                    \
        }                                                                     \
    }
#define STS_CHUNK(buf)                                                        \
    {                                                                         \
        _Pragma("unroll")                                                     \
        for (int i = 0; i < 4; i++) {                                         \
            int idx = tid + 256*i;                                            \
            int px = idx >> 3, c8 = idx & 7;                                  \
            float* da = &A_s[(buf)*A_BUF + px*A_STRIDE + c8*4];               \
            da[0] = __uint_as_float(f2tf32(pa[i].x));                         \
            da[1] = __uint_as_float(f2tf32(pa[i].y));                         \
            da[2] = __uint_as_float(f2tf32(pa[i].z));                         \
            da[3] = __uint_as_float(f2tf32(pa[i].w));                         \
            int n = idx >> 3, kq = idx & 7;                                   \
            float* db = &B_s[(buf)*B_BUF + n*B_STRIDE + kq*4];                \
            db[0] = __uint_as_float(f2tf32(pb[i].x));                         \
            db[1] = __uint_as_float(f2tf32(pb[i].y));                         \
            db[2] = __uint_as_float(f2tf32(pb[i].z));                         \
            db[3] = __uint_as_float(f2tf32(pb[i].w));                         \
        }                                                                     \
    }

    LDG_CHUNK(0);
    STS_CHUNK(0);
    __syncthreads();

    for (int q = 0; q < C_/KC; q++) {
        const int buf = q & 1;
        if (q < C_/KC - 1) LDG_CHUNK(q + 1);

        const float* Ab = A_s + buf*A_BUF;
        const float* Bb = B_s + buf*B_BUF;
#pragma unroll
        for (int ks = 0; ks < KC/8; ks++) {
            uint32_t af[4][4];
#pragma unroll
            for (int mf = 0; mf < 4; mf++) {
                int k = ks*8 + tg;
                int m = wm*64 + mf*16 + g;
                af[mf][0] = __float_as_uint(Ab[m*A_STRIDE + k]);
                af[mf][1] = __float_as_uint(Ab[(m+8)*A_STRIDE + k]);
                af[mf][2] = __float_as_uint(Ab[m*A_STRIDE + k + 4]);
                af[mf][3] = __float_as_uint(Ab[(m+8)*A_STRIDE + k + 4]);
            }
            uint32_t bf[4][2];
#pragma unroll
            for (int nf = 0; nf < 4; nf++) {
                int n = wn*32 + nf*8 + g;
                bf[nf][0] = __float_as_uint(Bb[n*B_STRIDE + ks*8 + tg]);
                bf[nf][1] = __float_as_uint(Bb[n*B_STRIDE + ks*8 + tg + 4]);
            }
#pragma unroll
            for (int mf = 0; mf < 4; mf++)
#pragma unroll
                for (int nf = 0; nf < 4; nf++)
                    MMA_TF32(acc[mf][nf], af[mf], bf[nf]);
        }

        if (q < C_/KC - 1) {
            STS_CHUNK(buf ^ 1);
            __syncthreads();
        }
    }

#pragma unroll
    for (int nf = 0; nf < 4; nf++) {
        int oc = o0 + wn*32 + nf*8 + 2*tg;
        float bp0 = __ldg(&b_pw[oc]);
        float bp1 = __ldg(&b_pw[oc + 1]);
        float* o_ptr0 = out + (size_t)(b*O_ + oc    )*HW_ + p0;
        float* o_ptr1 = out + (size_t)(b*O_ + oc + 1)*HW_ + p0;
#pragma unroll
        for (int mf = 0; mf < 4; mf++) {
            int m = wm*64 + mf*16 + g;
            o_ptr0[m]     = acc[mf][nf][0] + bp0;
            o_ptr1[m]     = acc[mf][nf][1] + bp1;
            o_ptr0[m + 8] = acc[mf][nf][2] + bp0;
            o_ptr1[m + 8] = acc[mf][nf][3] + bp1;
        }
    }
}

// ============================================================
extern "C" void kernel_launch(void* const* d_in, const int* in_sizes, int n_in,
                              void* d_out, int out_size)
{
    const float* x     = (const float*)d_in[0];
    const float* w_off = (const float*)d_in[1];
    const float* b_off = (const float*)d_in[2];
    const float* w_dw  = (const float*)d_in[3];
    const float* b_dw  = (const float*)d_in[4];
    const float* w_pw  = (const float*)d_in[5];
    const float* b_pw  = (const float*)d_in[6];
    float* out = (float*)d_out;

    cudaFuncSetAttribute(pw_mma_kernel,
                         cudaFuncAttributeMaxDynamicSharedMemorySize, PW_SMEM);
    cudaFuncSetAttribute(offset_mma_kernel,
                         cudaFuncAttributeMaxDynamicSharedMemorySize, OFF_SMEM);

    xpad_kernel<<<B_*64*H_, 132>>>(x);
    wt_kernel<<<80, 256>>>(w_off);

    dim3 gh(HW_/64, C_/32, B_);
    hwc_kernel<<<gh, 256>>>(x);

    dim3 g1(H_/2, B_);
    offset_mma_kernel<<<g1, 256, OFF_SMEM>>>();

    dim3 g1b(HW_/256, B_);
    param_kernel<<<g1b, 256>>>(b_off);

    dim3 g2(HW_/32, B_);
    sample_kernel<<<g2, 256>>>(w_dw, b_dw);

    dim3 g3((B_*HW_)/128, O_/128);
    pw_mma_kernel<<<g3, 256, PW_SMEM>>>(w_pw, b_pw, out);
}